// round 16
// baseline (speedup 1.0000x reference)
#include <cuda_runtime.h>
#include <cuda_bf16.h>
#include <cuda_fp16.h>
#include <cstdint>
#include <math.h>

#define BB 4
#define SS 1024
#define EE 768
#define HH 12
#define DD 64
#define MT (BB*SS)
#define SCALING 0.125f

// ---------------- device scratch (allocation-free rule) ----------------
__device__ __half g_Qh[BB*HH*SS*DD];      // Q: single fp16 (scaled)
__device__ __half g_Kh[BB*HH*SS*DD];      // K: single fp16
__device__ __half g_Vh[BB*HH*SS*DD];      // V: single fp16
__device__ __half g_Xh[MT*EE];            // X: single fp16
__device__ __half g_Wh[4*EE*EE];          // weights: single fp16
__device__ __half g_AOh[MT*EE];           // AO: single fp16

__device__ __forceinline__ uint32_t smem_u32(const void* p) {
    uint32_t a;
    asm("{ .reg .u64 t; cvta.to.shared.u64 t, %1; cvt.u32.u64 %0, t; }"
        : "=r"(a) : "l"(p));
    return a;
}

#define LDSM4(r, addr) \
    asm volatile("ldmatrix.sync.aligned.m8n8.x4.shared.b16 {%0,%1,%2,%3}, [%4];" \
        : "=r"((r)[0]), "=r"((r)[1]), "=r"((r)[2]), "=r"((r)[3]) : "r"(addr))
#define LDSM4T(r, addr) \
    asm volatile("ldmatrix.sync.aligned.m8n8.x4.trans.shared.b16 {%0,%1,%2,%3}, [%4];" \
        : "=r"((r)[0]), "=r"((r)[1]), "=r"((r)[2]), "=r"((r)[3]) : "r"(addr))

#define MMA_FP16(d, a, b0v, b1v) \
    asm volatile("mma.sync.aligned.m16n8k16.row.col.f32.f16.f16.f32 " \
        "{%0,%1,%2,%3}, {%4,%5,%6,%7}, {%8,%9}, {%0,%1,%2,%3};" \
        : "+f"((d)[0]), "+f"((d)[1]), "+f"((d)[2]), "+f"((d)[3]) \
        : "r"((a)[0]), "r"((a)[1]), "r"((a)[2]), "r"((a)[3]), "r"(b0v), "r"(b1v))

#define CP_ASYNC16(smem, gmem) \
    asm volatile("cp.async.cg.shared.global [%0], [%1], 16;" :: "r"(smem), "l"(gmem))
#define CP_COMMIT()  asm volatile("cp.async.commit_group;" ::: "memory")
#define CP_WAIT2()   asm volatile("cp.async.wait_group 2;" ::: "memory")
#define CP_WAIT3()   asm volatile("cp.async.wait_group 3;" ::: "memory")
#define CP_WAIT4()   asm volatile("cp.async.wait_group 4;" ::: "memory")

// ---------------------------------------------------------------------------
// convert: blocks [0,384) = X -> single fp16; then 4x72 = W -> single fp16
// ---------------------------------------------------------------------------
__global__ void __launch_bounds__(256) split_all_kernel(
    const float* __restrict__ X,
    const float* __restrict__ qw, const float* __restrict__ kw,
    const float* __restrict__ vw, const float* __restrict__ ow)
{
    const int bid = blockIdx.x;
    const float* src;
    __half* dst;
    size_t off;
    if (bid < 384) {
        src = X; dst = g_Xh; off = (size_t)bid * 8192;
    } else {
        int r = bid - 384;
        int slot = r / 72, rb = r % 72;
        src = (slot == 0) ? qw : (slot == 1) ? kw : (slot == 2) ? vw : ow;
        dst = g_Wh + (size_t)slot * EE * EE;
        off = (size_t)rb * 8192;
    }
    float4 v[8];
    #pragma unroll
    for (int u = 0; u < 8; u++)
        v[u] = *(const float4*)(src + off + u*1024 + threadIdx.x*4);
    #pragma unroll
    for (int u = 0; u < 8; u++) {
        size_t i = off + u*1024 + threadIdx.x*4;
        __half2 a = __floats2half2_rn(v[u].x, v[u].y);
        __half2 b = __floats2half2_rn(v[u].z, v[u].w);
        *(__half2*)(dst + i)     = a;
        *(__half2*)(dst + i + 2) = b;
    }
}

// ---------------------------------------------------------------------------
// HMMA GEMM (1-term fp16), templated on tile-M: D = A(M,K) @ W(N,K)^T.
// CTA tile TM x 128, 256 thr, 8 warps (2x4), warp tile (TM/2) x 32, BK=32.
// 6-stage cp.async pipeline with wait_group 4 (prefetch distance ~5 stages)
// to cover L2/DRAM latency — the K-loop was latency-bound at 3 stages.
// ---------------------------------------------------------------------------
#define NS (EE/32)       // 24 K-stages
#define DEPTH 6
template<int TM>
__global__ void __launch_bounds__(256, 2) gemm_mma_kernel(
    const float* __restrict__ b0p, const float* __restrict__ b1p,
    const float* __restrict__ b2p, float* __restrict__ outp,
    int wslot0, int is_qkv)
{
    extern __shared__ char dsm[];
    const uint32_t sbase = smem_u32(dsm);
    constexpr int NT = TM / 32;                    // m16-frags per warp
    constexpr uint32_t ASZ = (uint32_t)TM * 64u;   // A tile bytes
    constexpr uint32_t STG = ASZ + 8192u;          // A + B per stage

    const int tid = threadIdx.x;
    const int wid = tid >> 5, lane = tid & 31;
    const int warp_m = wid & 1, warp_n = wid >> 1;
    const int m0w = warp_m * (TM/2), n0w = warp_n * 32;

    const int z = is_qkv ? blockIdx.z : 0;
    const size_t woff = (size_t)(wslot0 + z) * EE * EE;
    const float* bias = (z == 0) ? b0p : (z == 1) ? b1p : b2p;
    const float scale = (is_qkv && z == 0) ? SCALING : 1.0f;
    __half* outH = (z == 0) ? g_Qh : (z == 1) ? g_Kh : g_Vh;

    const int n0 = blockIdx.x * 128;
    const int m0 = blockIdx.y * TM;

    const __half* s0 = (is_qkv ? g_Xh : g_AOh) + (size_t)m0 * EE;
    const __half* s2 = g_Wh + woff + (size_t)n0 * EE;

    const int lrow = tid >> 2;           // 0..63
    const int lch  = tid & 3;
    auto stage_load = [&](int k0, int stg) {
        uint32_t sb = sbase + (uint32_t)stg * STG;
        {   // A tile: TM rows
            const __half* sp = s0 + k0 + lch*8;
            #pragma unroll
            for (int j = 0; j < TM/64; j++) {
                int row = lrow + j*64;
                CP_ASYNC16(sb + row*64 + ((lch ^ ((row >> 1) & 3)) << 4),
                           sp + (size_t)row * EE);
            }
        }
        {   // B tile: 128 rows
            const __half* sp = s2 + k0 + lch*8;
            uint32_t tb = sb + ASZ;
            #pragma unroll
            for (int j = 0; j < 2; j++) {
                int row = lrow + j*64;
                CP_ASYNC16(tb + row*64 + ((lch ^ ((row >> 1) & 3)) << 4),
                           sp + (size_t)row * EE);
            }
        }
        CP_COMMIT();
    };

    const int arow_sw = (lane >> 1) & 3;
    const int brow7 = (lane & 7) + ((lane >> 4) << 3);
    const int brow_sw = (brow7 >> 1) & 3;
    uint32_t aoff[NT], boff[2];
    #pragma unroll
    for (int t = 0; t < NT; t++)
        aoff[t] = (uint32_t)(m0w + t*16 + (lane & 15)) * 64u;
    #pragma unroll
    for (int p = 0; p < 2; p++)
        boff[p] = (uint32_t)(n0w + p*16 + brow7) * 64u;
    const int achk = lane >> 4;
    const int bchk = (lane >> 3) & 1;

    float acc[NT][4][4] = {};

    // prologue: fill 5 of 6 stages
    #pragma unroll
    for (int s = 0; s < DEPTH - 1; s++)
        stage_load(s * 32, s);

    #pragma unroll 1
    for (int s = 0; s < NS; s++) {
        CP_WAIT4();              // group s complete (4 newer groups in flight)
        __syncthreads();
        if (s + DEPTH - 1 < NS)
            stage_load((s + DEPTH - 1) * 32, (s + DEPTH - 1) % DEPTH);
        else
            CP_COMMIT();         // empty group keeps wait arithmetic exact

        const uint32_t stg = sbase + (uint32_t)(s % DEPTH) * STG;
        const uint32_t Ah_ = stg;
        const uint32_t Bh  = stg + ASZ;

        #pragma unroll
        for (int ks = 0; ks < 2; ks++) {
            const uint32_t asw = (uint32_t)((2*ks + achk) ^ arow_sw) << 4;
            const uint32_t bsw = (uint32_t)((2*ks + bchk) ^ brow_sw) << 4;
            uint32_t B[2][4];
            #pragma unroll
            for (int p = 0; p < 2; p++)
                LDSM4(B[p], Bh + boff[p] + bsw);
            #pragma unroll
            for (int t = 0; t < NT; t++) {
                uint32_t A[4];
                LDSM4(A, Ah_ + aoff[t] + asw);
                #pragma unroll
                for (int n = 0; n < 4; n++) {
                    const int p = n >> 1, q = (n & 1) * 2;
                    MMA_FP16(acc[t][n], A, B[p][q], B[p][q+1]);
                }
            }
        }
    }

    // epilogue
    const int rl = lane >> 2, cl2 = (lane & 3) * 2;
    #pragma unroll
    for (int t = 0; t < NT; t++)
        #pragma unroll
        for (int n = 0; n < 4; n++) {
            const int col = n0 + n0w + n*8 + cl2;
            #pragma unroll
            for (int half = 0; half < 2; half++) {
                const int row = m0 + m0w + t*16 + rl + half*8;
                float ox = (acc[t][n][half*2+0] + bias[col+0]) * scale;
                float oy = (acc[t][n][half*2+1] + bias[col+1]) * scale;
                if (is_qkv) {
                    const int hh = col >> 6, d0 = col & 63;
                    const int bb_ = row >> 10, ss_ = row & 1023;
                    size_t idx = ((size_t)((bb_*HH + hh)*SS + ss_))*DD + d0;
                    *(__half2*)(outH + idx) = __floats2half2_rn(ox, oy);
                } else {
                    float2 o; o.x = ox; o.y = oy;
                    *(float2*)(outp + (size_t)row * EE + col) = o;
                }
            }
        }
}

// ---------------------------------------------------------------------------
// Flash attention, all 1-term fp16: S = Q·K, O = P·V, fp32 accumulate.
// CTA = 128 Q rows x (b,h). 8 warps, warp = m16 x n64.
// 4 KV stages, wait_group 2 (3 KV loads in flight).
// Smem: Q 16KB | 4 x 16KB KV stages | pk 4KB = 84KB.
// ---------------------------------------------------------------------------
__global__ void __launch_bounds__(256, 2) attn_mma_kernel(
    const int* __restrict__ pos_row, const int* __restrict__ pos_col,
    const float* __restrict__ rel_table)
{
    extern __shared__ char dsm[];
    const uint32_t sbase = smem_u32(dsm);
    const uint32_t sQ = sbase;
    int* pk = (int*)(dsm + 16384 + 4*16384);

    const int tid = threadIdx.x;
    const int wid = tid >> 5, lane = tid & 31;
    const int l7 = lane & 7;
    const int rl = lane >> 2, cl2 = (lane & 3) * 2;
    const int achk = lane >> 4;
    const int bchk = (lane >> 3) & 1;

    const int q0 = blockIdx.x * 128;
    const int h = blockIdx.y, b = blockIdx.z;
    const size_t hb = (size_t)(b*HH + h) * SS * DD;

    #pragma unroll
    for (int i = 0; i < 4; i++) {
        int s = tid + i*256;
        pk[s] = (pos_row[b*SS + s] << 5) | pos_col[b*SS + s];
    }

    // Q stage: 128 rows x 64 fp16 = 16KB (group 0)
    {
        const int r = tid & 127, hf = tid >> 7;
        const __half* src = g_Qh + hb + (size_t)(q0 + r)*DD;
        uint32_t dstrow = sQ + (uint32_t)r * 128u;
        #pragma unroll
        for (int j = 0; j < 4; j++) {
            int ch = hf*4 + j;
            CP_ASYNC16(dstrow + ((ch ^ (r & 7)) << 4), src + ch*8);
        }
        CP_COMMIT();
    }

    // KV stage: K 8KB + V 8KB = 16KB per stage
    auto kv_load = [&](int kb, int stg) {
        const int t = tid >> 7;
        const int r = tid & 63;
        const int hf = (tid >> 6) & 1;
        const __half* src = (t == 0 ? g_Kh : g_Vh) + hb + (size_t)(kb + r)*DD;
        uint32_t dstrow = sbase + 16384u + (uint32_t)stg*16384u
                        + (uint32_t)t*8192u + (uint32_t)r*128u;
        #pragma unroll
        for (int j = 0; j < 4; j++) {
            int ch = hf*4 + j;
            CP_ASYNC16(dstrow + ((ch ^ (r & 7)) << 4), src + ch*8);
        }
        CP_COMMIT();
    };
    kv_load(0, 0);
    kv_load(64, 1);
    kv_load(128, 2);

    CP_WAIT3();          // Q done (3 KV groups still in flight)
    __syncthreads();

    uint32_t qh[4][4];
    const uint32_t aq = (uint32_t)(wid*16 + (lane & 15)) * 128u;
    #pragma unroll
    for (int ks = 0; ks < 4; ks++) {
        uint32_t sw = (uint32_t)((2*ks + achk) ^ l7) << 4;
        LDSM4(qh[ks], sQ + aq + sw);
    }

    const int rq0 = pk[q0 + wid*16 + rl];
    const int rq1 = pk[q0 + wid*16 + rl + 8];
    const float tb0 = rel_table[0*HH + h];
    const float tb1 = rel_table[1*HH + h];
    const float tb2 = rel_table[2*HH + h];
    const float tb3 = rel_table[3*HH + h];

    float oacc[8][4] = {};
    float m0 = -1e30f, m1 = -1e30f, l0 = 0.f, l1 = 0.f;

    #pragma unroll 1
    for (int kt = 0; kt < SS/64; kt++) {
        CP_WAIT2();      // kv[kt] done (kv[kt+1..kt+3] in flight)
        __syncthreads();
        if (kt + 3 < SS/64)
            kv_load((kt + 3) * 64, (kt + 3) & 3);
        else
            CP_COMMIT();

        const uint32_t st = sbase + 16384u + (uint32_t)(kt & 3) * 16384u;
        const uint32_t Kt = st, Vt = st + 8192u;

        // S = Q K^T  (m16 x n64), fp32 accum
        float sacc[8][4] = {};
        #pragma unroll
        for (int ks = 0; ks < 4; ks++) {
            const uint32_t bsw = (uint32_t)((2*ks + bchk) ^ l7) << 4;
            #pragma unroll
            for (int p = 0; p < 4; p++) {
                const uint32_t bo =
                    (uint32_t)(p*16 + l7 + ((lane >> 4) << 3)) * 128u + bsw;
                uint32_t B[4];
                LDSM4(B, Kt + bo);
                MMA_FP16(sacc[2*p],   qh[ks], B[0], B[1]);
                MMA_FP16(sacc[2*p+1], qh[ks], B[2], B[3]);
            }
        }

        // bias
        const int kb = kt * 64;
        #pragma unroll
        for (int t = 0; t < 8; t++) {
            int c0 = kb + t*8 + cl2;
            int rk0 = pk[c0], rk1 = pk[c0 + 1];
            int x;
            x = rq0 ^ rk0; sacc[t][0] += (x < 32) ? (((x & 31) == 0) ? tb3 : tb1)
                                                  : (((x & 31) == 0) ? tb2 : tb0);
            x = rq0 ^ rk1; sacc[t][1] += (x < 32) ? (((x & 31) == 0) ? tb3 : tb1)
                                                  : (((x & 31) == 0) ? tb2 : tb0);
            x = rq1 ^ rk0; sacc[t][2] += (x < 32) ? (((x & 31) == 0) ? tb3 : tb1)
                                                  : (((x & 31) == 0) ? tb2 : tb0);
            x = rq1 ^ rk1; sacc[t][3] += (x < 32) ? (((x & 31) == 0) ? tb3 : tb1)
                                                  : (((x & 31) == 0) ? tb2 : tb0);
        }

        // online softmax (MUFU exp; 4 lanes/row)
        float mx0 = sacc[0][0], mx1 = sacc[0][2];
        #pragma unroll
        for (int t = 0; t < 8; t++) {
            mx0 = fmaxf(mx0, fmaxf(sacc[t][0], sacc[t][1]));
            mx1 = fmaxf(mx1, fmaxf(sacc[t][2], sacc[t][3]));
        }
        mx0 = fmaxf(mx0, __shfl_xor_sync(0xffffffffu, mx0, 1));
        mx0 = fmaxf(mx0, __shfl_xor_sync(0xffffffffu, mx0, 2));
        mx1 = fmaxf(mx1, __shfl_xor_sync(0xffffffffu, mx1, 1));
        mx1 = fmaxf(mx1, __shfl_xor_sync(0xffffffffu, mx1, 2));
        float mn0 = fmaxf(m0, mx0), mn1 = fmaxf(m1, mx1);
        float sc0 = __expf(m0 - mn0), sc1 = __expf(m1 - mn1);
        m0 = mn0; m1 = mn1;
        float rs0 = 0.f, rs1 = 0.f;
        #pragma unroll
        for (int t = 0; t < 8; t++) {
            sacc[t][0] = __expf(sacc[t][0] - mn0);
            sacc[t][1] = __expf(sacc[t][1] - mn0);
            sacc[t][2] = __expf(sacc[t][2] - mn1);
            sacc[t][3] = __expf(sacc[t][3] - mn1);
            rs0 += sacc[t][0] + sacc[t][1];
            rs1 += sacc[t][2] + sacc[t][3];
        }
        rs0 += __shfl_xor_sync(0xffffffffu, rs0, 1);
        rs0 += __shfl_xor_sync(0xffffffffu, rs0, 2);
        rs1 += __shfl_xor_sync(0xffffffffu, rs1, 1);
        rs1 += __shfl_xor_sync(0xffffffffu, rs1, 2);
        l0 = l0 * sc0 + rs0;
        l1 = l1 * sc1 + rs1;
        #pragma unroll
        for (int t = 0; t < 8; t++) {
            oacc[t][0] *= sc0; oacc[t][1] *= sc0;
            oacc[t][2] *= sc1; oacc[t][3] *= sc1;
        }

        // O += P V : P single fp16 from sacc
        #pragma unroll
        for (int ks = 0; ks < 4; ks++) {
            uint32_t ph[4];
            __half2 h2;
            h2 = __floats2half2_rn(sacc[2*ks][0],   sacc[2*ks][1]);   ph[0] = *(uint32_t*)&h2;
            h2 = __floats2half2_rn(sacc[2*ks][2],   sacc[2*ks][3]);   ph[1] = *(uint32_t*)&h2;
            h2 = __floats2half2_rn(sacc[2*ks+1][0], sacc[2*ks+1][1]); ph[2] = *(uint32_t*)&h2;
            h2 = __floats2half2_rn(sacc[2*ks+1][2], sacc[2*ks+1][3]); ph[3] = *(uint32_t*)&h2;
            const uint32_t vr =
                (uint32_t)(ks*16 + l7 + (((lane >> 3) & 1) << 3)) * 128u;
            #pragma unroll
            for (int p = 0; p < 4; p++) {
                const uint32_t vsw = (uint32_t)((2*p + achk) ^ l7) << 4;
                uint32_t V[4];
                LDSM4T(V, Vt + vr + vsw);
                MMA_FP16(oacc[2*p],   ph, V[0], V[1]);
                MMA_FP16(oacc[2*p+1], ph, V[2], V[3]);
            }
        }
    }

    // epilogue: normalize, emit single fp16 AO at [B,S,E] (e = h*64+d)
    const float inv0 = 1.0f / l0, inv1 = 1.0f / l1;
    const int qrow0 = q0 + wid*16 + rl;
    #pragma unroll
    for (int t = 0; t < 8; t++) {
        const int e = h*64 + t*8 + cl2;
        size_t i0 = (size_t)(b*SS + qrow0) * EE + e;
        size_t i1 = (size_t)(b*SS + qrow0 + 8) * EE + e;
        *(__half2*)(g_AOh + i0) = __floats2half2_rn(oacc[t][0]*inv0, oacc[t][1]*inv0);
        *(__half2*)(g_AOh + i1) = __floats2half2_rn(oacc[t][2]*inv1, oacc[t][3]*inv1);
    }
}

// ---------------------------------------------------------------------------
extern "C" void kernel_launch(void* const* d_in, const int* in_sizes, int n_in,
                              void* d_out, int out_size) {
    const float* X  = (const float*)d_in[0];
    const int*   pr = (const int*)  d_in[1];
    const int*   pc = (const int*)  d_in[2];
    const float* qw = (const float*)d_in[3];
    const float* qb = (const float*)d_in[4];
    const float* kw = (const float*)d_in[5];
    const float* kb = (const float*)d_in[6];
    const float* vw = (const float*)d_in[7];
    const float* vb = (const float*)d_in[8];
    const float* ow = (const float*)d_in[9];
    const float* ob = (const float*)d_in[10];
    const float* rt = (const float*)d_in[11];
    float* out = (float*)d_out;

    const int DSMEM_G128 = 6 * 16384;   // TM=128: 16KB/stage x 6
    const int DSMEM_G64  = 6 * 12288;   // TM=64:  12KB/stage x 6
    cudaFuncSetAttribute(gemm_mma_kernel<128>,
                         cudaFuncAttributeMaxDynamicSharedMemorySize, DSMEM_G128);
    cudaFuncSetAttribute(gemm_mma_kernel<64>,
                         cudaFuncAttributeMaxDynamicSharedMemorySize, DSMEM_G64);
    const int DSMEM_A = 16384 + 4*16384 + 4096;    // 86016
    cudaFuncSetAttribute(attn_mma_kernel,
                         cudaFuncAttributeMaxDynamicSharedMemorySize, DSMEM_A);

    split_all_kernel<<<384 + 4*72, 256>>>(X, qw, kw, vw, ow);

    dim3 g1(EE/128, MT/128, 3);
    gemm_mma_kernel<128><<<g1, 256, DSMEM_G128>>>(qb, kb, vb, nullptr, 0, 1);

    dim3 g2(SS/128, HH, BB);
    attn_mma_kernel<<<g2, 256, DSMEM_A>>>(pr, pc, rt);

    dim3 g3(EE/128, MT/64, 1);
    gemm_mma_kernel<64><<<g3, 256, DSMEM_G64>>>(ob, ob, ob, out, 3, 0);
}

// round 17
// speedup vs baseline: 1.0412x; 1.0412x over previous
#include <cuda_runtime.h>
#include <cuda_bf16.h>
#include <cuda_fp16.h>
#include <cstdint>
#include <math.h>

#define BB 4
#define SS 1024
#define EE 768
#define HH 12
#define DD 64
#define MT (BB*SS)
#define SCALING 0.125f
#define L2E 1.4426950408889634f

// ---------------- device scratch (allocation-free rule) ----------------
__device__ __half g_Qh[BB*HH*SS*DD];      // Q: single fp16 (scaled)
__device__ __half g_Kh[BB*HH*SS*DD];      // K: single fp16
__device__ __half g_Vh[BB*HH*SS*DD];      // V: single fp16
__device__ __half g_Xh[MT*EE];            // X: single fp16
__device__ __half g_Wh[4*EE*EE];          // weights: single fp16
__device__ __half g_AOh[MT*EE];           // AO: single fp16

__device__ __forceinline__ uint32_t smem_u32(const void* p) {
    uint32_t a;
    asm("{ .reg .u64 t; cvta.to.shared.u64 t, %1; cvt.u32.u64 %0, t; }"
        : "=r"(a) : "l"(p));
    return a;
}

#define LDSM4(r, addr) \
    asm volatile("ldmatrix.sync.aligned.m8n8.x4.shared.b16 {%0,%1,%2,%3}, [%4];" \
        : "=r"((r)[0]), "=r"((r)[1]), "=r"((r)[2]), "=r"((r)[3]) : "r"(addr))
#define LDSM4T(r, addr) \
    asm volatile("ldmatrix.sync.aligned.m8n8.x4.trans.shared.b16 {%0,%1,%2,%3}, [%4];" \
        : "=r"((r)[0]), "=r"((r)[1]), "=r"((r)[2]), "=r"((r)[3]) : "r"(addr))

#define MMA_FP16(d, a, b0v, b1v) \
    asm volatile("mma.sync.aligned.m16n8k16.row.col.f32.f16.f16.f32 " \
        "{%0,%1,%2,%3}, {%4,%5,%6,%7}, {%8,%9}, {%0,%1,%2,%3};" \
        : "+f"((d)[0]), "+f"((d)[1]), "+f"((d)[2]), "+f"((d)[3]) \
        : "r"((a)[0]), "r"((a)[1]), "r"((a)[2]), "r"((a)[3]), "r"(b0v), "r"(b1v))

#define CP_ASYNC16(smem, gmem) \
    asm volatile("cp.async.cg.shared.global [%0], [%1], 16;" :: "r"(smem), "l"(gmem))
#define CP_COMMIT()  asm volatile("cp.async.commit_group;" ::: "memory")
#define CP_WAIT0()   asm volatile("cp.async.wait_group 0;" ::: "memory")
#define CP_WAIT1()   asm volatile("cp.async.wait_group 1;" ::: "memory")

// (t1, t0) fp32 -> fp16x2 (lo = t0), then 2^x on both lanes in ONE MUFU op
__device__ __forceinline__ uint32_t exp2pack(float t0, float t1) {
    uint32_t r;
    asm("cvt.rn.f16x2.f32 %0, %1, %2;" : "=r"(r) : "f"(t1), "f"(t0));
    asm("ex2.approx.f16x2 %0, %0;" : "+r"(r));
    return r;
}

// ---------------------------------------------------------------------------
// convert: blocks [0,384) = X -> single fp16; then 4x72 = W -> single fp16
// ---------------------------------------------------------------------------
__global__ void __launch_bounds__(256) split_all_kernel(
    const float* __restrict__ X,
    const float* __restrict__ qw, const float* __restrict__ kw,
    const float* __restrict__ vw, const float* __restrict__ ow)
{
    const int bid = blockIdx.x;
    const float* src;
    __half* dst;
    size_t off;
    if (bid < 384) {
        src = X; dst = g_Xh; off = (size_t)bid * 8192;
    } else {
        int r = bid - 384;
        int slot = r / 72, rb = r % 72;
        src = (slot == 0) ? qw : (slot == 1) ? kw : (slot == 2) ? vw : ow;
        dst = g_Wh + (size_t)slot * EE * EE;
        off = (size_t)rb * 8192;
    }
    float4 v[8];
    #pragma unroll
    for (int u = 0; u < 8; u++)
        v[u] = *(const float4*)(src + off + u*1024 + threadIdx.x*4);
    #pragma unroll
    for (int u = 0; u < 8; u++) {
        size_t i = off + u*1024 + threadIdx.x*4;
        __half2 a = __floats2half2_rn(v[u].x, v[u].y);
        __half2 b = __floats2half2_rn(v[u].z, v[u].w);
        *(__half2*)(dst + i)     = a;
        *(__half2*)(dst + i + 2) = b;
    }
}

// ---------------------------------------------------------------------------
// HMMA GEMM (1-term fp16): D = A(M,K) @ W(N,K)^T, fp32 accum.
// CTA 128x128, 8 warps (2x4), warp tile 64x32, BK=32, 3-stage cp.async.
// (R14 config — proven best; pipeline depth and tile-M probes were neutral.)
// ---------------------------------------------------------------------------
#define NS (EE/32)       // 24 K-stages
#define STG_B 16384u     // A + W tiles per stage
__global__ void __launch_bounds__(256, 2) gemm_mma_kernel(
    const float* __restrict__ b0p, const float* __restrict__ b1p,
    const float* __restrict__ b2p, float* __restrict__ outp,
    int wslot0, int is_qkv)
{
    extern __shared__ char dsm[];
    const uint32_t sbase = smem_u32(dsm);

    const int tid = threadIdx.x;
    const int wid = tid >> 5, lane = tid & 31;
    const int warp_m = wid & 1, warp_n = wid >> 1;
    const int m0w = warp_m * 64, n0w = warp_n * 32;

    const int z = is_qkv ? blockIdx.z : 0;
    const size_t woff = (size_t)(wslot0 + z) * EE * EE;
    const float* bias = (z == 0) ? b0p : (z == 1) ? b1p : b2p;
    const float scale = (is_qkv && z == 0) ? SCALING : 1.0f;
    __half* outH = (z == 0) ? g_Qh : (z == 1) ? g_Kh : g_Vh;

    const int n0 = blockIdx.x * 128;
    const int m0 = blockIdx.y * 128;

    const __half* s0 = (is_qkv ? g_Xh : g_AOh) + (size_t)m0 * EE;
    const __half* s2 = g_Wh + woff + (size_t)n0 * EE;

    const int lrow = tid >> 2;
    const int lch  = tid & 3;
    auto stage_load = [&](int k0, int stg) {
        uint32_t sb = sbase + (uint32_t)stg * STG_B;
        #pragma unroll
        for (int t = 0; t < 2; t++) {
            const __half* sp = (t == 0 ? s0 : s2) + k0 + lch*8;
            uint32_t tb = sb + (uint32_t)t * 8192u;
            #pragma unroll
            for (int j = 0; j < 2; j++) {
                int row = lrow + j*64;
                CP_ASYNC16(tb + row*64 + ((lch ^ ((row >> 1) & 3)) << 4),
                           sp + (size_t)row * EE);
            }
        }
        CP_COMMIT();
    };

    const int arow_sw = (lane >> 1) & 3;
    const int brow7 = (lane & 7) + ((lane >> 4) << 3);
    const int brow_sw = (brow7 >> 1) & 3;
    uint32_t aoff[4], boff[2];
    #pragma unroll
    for (int t = 0; t < 4; t++)
        aoff[t] = (uint32_t)(m0w + t*16 + (lane & 15)) * 64u;
    #pragma unroll
    for (int p = 0; p < 2; p++)
        boff[p] = (uint32_t)(n0w + p*16 + brow7) * 64u;
    const int achk = lane >> 4;
    const int bchk = (lane >> 3) & 1;

    float acc[4][4][4] = {};

    stage_load(0, 0);
    stage_load(32, 1);

    #pragma unroll 1
    for (int s = 0; s < NS; s++) {
        if (s == NS - 1) { CP_WAIT0(); } else { CP_WAIT1(); }
        __syncthreads();
        if (s + 2 < NS) stage_load((s + 2) * 32, (s + 2) % 3);

        const uint32_t stg = sbase + (uint32_t)(s % 3) * STG_B;
        const uint32_t Ah_ = stg;
        const uint32_t Bh  = stg + 8192u;

        #pragma unroll
        for (int ks = 0; ks < 2; ks++) {
            const uint32_t asw = (uint32_t)((2*ks + achk) ^ arow_sw) << 4;
            const uint32_t bsw = (uint32_t)((2*ks + bchk) ^ brow_sw) << 4;
            uint32_t B[2][4];
            #pragma unroll
            for (int p = 0; p < 2; p++)
                LDSM4(B[p], Bh + boff[p] + bsw);
            #pragma unroll
            for (int t = 0; t < 4; t++) {
                uint32_t A[4];
                LDSM4(A, Ah_ + aoff[t] + asw);
                #pragma unroll
                for (int n = 0; n < 4; n++) {
                    const int p = n >> 1, q = (n & 1) * 2;
                    MMA_FP16(acc[t][n], A, B[p][q], B[p][q+1]);
                }
            }
        }
    }

    // epilogue
    const int rl = lane >> 2, cl2 = (lane & 3) * 2;
    #pragma unroll
    for (int t = 0; t < 4; t++)
        #pragma unroll
        for (int n = 0; n < 4; n++) {
            const int col = n0 + n0w + n*8 + cl2;
            #pragma unroll
            for (int half = 0; half < 2; half++) {
                const int row = m0 + m0w + t*16 + rl + half*8;
                float ox = (acc[t][n][half*2+0] + bias[col+0]) * scale;
                float oy = (acc[t][n][half*2+1] + bias[col+1]) * scale;
                if (is_qkv) {
                    const int hh = col >> 6, d0 = col & 63;
                    const int bb_ = row >> 10, ss_ = row & 1023;
                    size_t idx = ((size_t)((bb_*HH + hh)*SS + ss_))*DD + d0;
                    *(__half2*)(outH + idx) = __floats2half2_rn(ox, oy);
                } else {
                    float2 o; o.x = ox; o.y = oy;
                    *(float2*)(outp + (size_t)row * EE + col) = o;
                }
            }
        }
}

// ---------------------------------------------------------------------------
// Flash attention, 1-term fp16 MMAs, softmax on ex2.approx.f16x2 (2 exps per
// MUFU op, result IS the P fragment) and l accumulated via ones-column MMA
// (consistent with fp16 P; no shuffle reduction). fp32 accumulate.
// CTA = 128 Q rows x (b,h). 8 warps, warp = m16 x n64.
// Smem: Q 16KB | 2 x 16KB KV stages | pk 4KB.
// ---------------------------------------------------------------------------
__global__ void __launch_bounds__(256, 2) attn_mma_kernel(
    const int* __restrict__ pos_row, const int* __restrict__ pos_col,
    const float* __restrict__ rel_table)
{
    extern __shared__ char dsm[];
    const uint32_t sbase = smem_u32(dsm);
    const uint32_t sQ = sbase;
    int* pk = (int*)(dsm + 49152);

    const int tid = threadIdx.x;
    const int wid = tid >> 5, lane = tid & 31;
    const int l7 = lane & 7;
    const int rl = lane >> 2, cl2 = (lane & 3) * 2;
    const int achk = lane >> 4;
    const int bchk = (lane >> 3) & 1;
    const uint32_t ONES = 0x3C003C00u;   // fp16x2 {1.0, 1.0}

    const int q0 = blockIdx.x * 128;
    const int h = blockIdx.y, b = blockIdx.z;
    const size_t hb = (size_t)(b*HH + h) * SS * DD;

    #pragma unroll
    for (int i = 0; i < 4; i++) {
        int s = tid + i*256;
        pk[s] = (pos_row[b*SS + s] << 5) | pos_col[b*SS + s];
    }

    // Q stage: 128 rows x 64 fp16 = 16KB
    {
        const int r = tid & 127, hf = tid >> 7;
        const __half* src = g_Qh + hb + (size_t)(q0 + r)*DD;
        uint32_t dstrow = sQ + (uint32_t)r * 128u;
        #pragma unroll
        for (int j = 0; j < 4; j++) {
            int ch = hf*4 + j;
            CP_ASYNC16(dstrow + ((ch ^ (r & 7)) << 4), src + ch*8);
        }
        CP_COMMIT();
    }

    // KV stage: K 8KB + V 8KB = 16KB per stage
    auto kv_load = [&](int kb, int stg) {
        const int t = tid >> 7;
        const int r = tid & 63;
        const int hf = (tid >> 6) & 1;
        const __half* src = (t == 0 ? g_Kh : g_Vh) + hb + (size_t)(kb + r)*DD;
        uint32_t dstrow = sbase + 16384u + (uint32_t)stg*16384u
                        + (uint32_t)t*8192u + (uint32_t)r*128u;
        #pragma unroll
        for (int j = 0; j < 4; j++) {
            int ch = hf*4 + j;
            CP_ASYNC16(dstrow + ((ch ^ (r & 7)) << 4), src + ch*8);
        }
        CP_COMMIT();
    };
    kv_load(0, 0);

    CP_WAIT1();
    __syncthreads();

    uint32_t qh[4][4];
    const uint32_t aq = (uint32_t)(wid*16 + (lane & 15)) * 128u;
    #pragma unroll
    for (int ks = 0; ks < 4; ks++) {
        uint32_t sw = (uint32_t)((2*ks + achk) ^ l7) << 4;
        LDSM4(qh[ks], sQ + aq + sw);
    }

    const int rq0 = pk[q0 + wid*16 + rl];
    const int rq1 = pk[q0 + wid*16 + rl + 8];
    const float tb0 = rel_table[0*HH + h];
    const float tb1 = rel_table[1*HH + h];
    const float tb2 = rel_table[2*HH + h];
    const float tb3 = rel_table[3*HH + h];

    float oacc[8][4] = {};
    float lacc[4] = {};                 // ones-MMA row-sum accumulator
    float m0 = -1e30f, m1 = -1e30f;

    #pragma unroll 1
    for (int kt = 0; kt < SS/64; kt++) {
        CP_WAIT0();
        __syncthreads();
        if (kt + 1 < SS/64) kv_load((kt + 1) * 64, (kt + 1) & 1);

        const uint32_t st = sbase + 16384u + (uint32_t)(kt & 1) * 16384u;
        const uint32_t Kt = st, Vt = st + 8192u;

        // S = Q K^T  (m16 x n64), fp32 accum
        float sacc[8][4] = {};
        #pragma unroll
        for (int ks = 0; ks < 4; ks++) {
            const uint32_t bsw = (uint32_t)((2*ks + bchk) ^ l7) << 4;
            #pragma unroll
            for (int p = 0; p < 4; p++) {
                const uint32_t bo =
                    (uint32_t)(p*16 + l7 + ((lane >> 4) << 3)) * 128u + bsw;
                uint32_t B[4];
                LDSM4(B, Kt + bo);
                MMA_FP16(sacc[2*p],   qh[ks], B[0], B[1]);
                MMA_FP16(sacc[2*p+1], qh[ks], B[2], B[3]);
            }
        }

        // bias (in place)
        const int kb = kt * 64;
        #pragma unroll
        for (int t = 0; t < 8; t++) {
            int c0 = kb + t*8 + cl2;
            int rk0 = pk[c0], rk1 = pk[c0 + 1];
            int x;
            x = rq0 ^ rk0; sacc[t][0] += (x < 32) ? (((x & 31) == 0) ? tb3 : tb1)
                                                  : (((x & 31) == 0) ? tb2 : tb0);
            x = rq0 ^ rk1; sacc[t][1] += (x < 32) ? (((x & 31) == 0) ? tb3 : tb1)
                                                  : (((x & 31) == 0) ? tb2 : tb0);
            x = rq1 ^ rk0; sacc[t][2] += (x < 32) ? (((x & 31) == 0) ? tb3 : tb1)
                                                  : (((x & 31) == 0) ? tb2 : tb0);
            x = rq1 ^ rk1; sacc[t][3] += (x < 32) ? (((x & 31) == 0) ? tb3 : tb1)
                                                  : (((x & 31) == 0) ? tb2 : tb0);
        }

        // row max + rescale (no sum reduction needed — l comes from ones-MMA)
        float mx0 = sacc[0][0], mx1 = sacc[0][2];
        #pragma unroll
        for (int t = 0; t < 8; t++) {
            mx0 = fmaxf(mx0, fmaxf(sacc[t][0], sacc[t][1]));
            mx1 = fmaxf(mx1, fmaxf(sacc[t][2], sacc[t][3]));
        }
        mx0 = fmaxf(mx0, __shfl_xor_sync(0xffffffffu, mx0, 1));
        mx0 = fmaxf(mx0, __shfl_xor_sync(0xffffffffu, mx0, 2));
        mx1 = fmaxf(mx1, __shfl_xor_sync(0xffffffffu, mx1, 1));
        mx1 = fmaxf(mx1, __shfl_xor_sync(0xffffffffu, mx1, 2));
        float mn0 = fmaxf(m0, mx0), mn1 = fmaxf(m1, mx1);
        float sc0 = __expf(m0 - mn0), sc1 = __expf(m1 - mn1);
        m0 = mn0; m1 = mn1;
        #pragma unroll
        for (int t = 0; t < 8; t++) {
            oacc[t][0] *= sc0; oacc[t][1] *= sc0;
            oacc[t][2] *= sc1; oacc[t][3] *= sc1;
        }
        lacc[0] *= sc0; lacc[1] *= sc0;
        lacc[2] *= sc1; lacc[3] *= sc1;

        // P = 2^(S*log2e - m*log2e) as fp16x2 (one MUFU per pair);
        // l += P @ ones via MMA; O += P V.
        const float mL0 = mn0 * L2E, mL1 = mn1 * L2E;
        #pragma unroll
        for (int ks = 0; ks < 4; ks++) {
            uint32_t ph[4];
            ph[0] = exp2pack(fmaf(sacc[2*ks][0],   L2E, -mL0),
                             fmaf(sacc[2*ks][1],   L2E, -mL0));
            ph[1] = exp2pack(fmaf(sacc[2*ks][2],   L2E, -mL1),
                             fmaf(sacc[2*ks][3],   L2E, -mL1));
            ph[2] = exp2pack(fmaf(sacc[2*ks+1][0], L2E, -mL0),
                             fmaf(sacc[2*ks+1][1], L2E, -mL0));
            ph[3] = exp2pack(fmaf(sacc[2*ks+1][2], L2E, -mL1),
                             fmaf(sacc[2*ks+1][3], L2E, -mL1));
            MMA_FP16(lacc, ph, ONES, ONES);
            const uint32_t vr =
                (uint32_t)(ks*16 + l7 + (((lane >> 3) & 1) << 3)) * 128u;
            #pragma unroll
            for (int p = 0; p < 4; p++) {
                const uint32_t vsw = (uint32_t)((2*p + achk) ^ l7) << 4;
                uint32_t V[4];
                LDSM4T(V, Vt + vr + vsw);
                MMA_FP16(oacc[2*p],   ph, V[0], V[1]);
                MMA_FP16(oacc[2*p+1], ph, V[2], V[3]);
            }
        }
    }

    // epilogue: normalize by ones-MMA row sums, emit fp16 AO at [B,S,E]
    const float inv0 = 1.0f / lacc[0], inv1 = 1.0f / lacc[2];
    const int qrow0 = q0 + wid*16 + rl;
    #pragma unroll
    for (int t = 0; t < 8; t++) {
        const int e = h*64 + t*8 + cl2;
        size_t i0 = (size_t)(b*SS + qrow0) * EE + e;
        size_t i1 = (size_t)(b*SS + qrow0 + 8) * EE + e;
        *(__half2*)(g_AOh + i0) = __floats2half2_rn(oacc[t][0]*inv0, oacc[t][1]*inv0);
        *(__half2*)(g_AOh + i1) = __floats2half2_rn(oacc[t][2]*inv1, oacc[t][3]*inv1);
    }
}

// ---------------------------------------------------------------------------
extern "C" void kernel_launch(void* const* d_in, const int* in_sizes, int n_in,
                              void* d_out, int out_size) {
    const float* X  = (const float*)d_in[0];
    const int*   pr = (const int*)  d_in[1];
    const int*   pc = (const int*)  d_in[2];
    const float* qw = (const float*)d_in[3];
    const float* qb = (const float*)d_in[4];
    const float* kw = (const float*)d_in[5];
    const float* kb = (const float*)d_in[6];
    const float* vw = (const float*)d_in[7];
    const float* vb = (const float*)d_in[8];
    const float* ow = (const float*)d_in[9];
    const float* ob = (const float*)d_in[10];
    const float* rt = (const float*)d_in[11];
    float* out = (float*)d_out;

    const int DSMEM_G = 3 * 16384;                 // 3-stage, 16KB/stage
    cudaFuncSetAttribute(gemm_mma_kernel,
                         cudaFuncAttributeMaxDynamicSharedMemorySize, DSMEM_G);
    const int DSMEM_A = 16384 + 2*16384 + 4096;    // 53248
    cudaFuncSetAttribute(attn_mma_kernel,
                         cudaFuncAttributeMaxDynamicSharedMemorySize, DSMEM_A);

    split_all_kernel<<<384 + 4*72, 256>>>(X, qw, kw, vw, ow);

    dim3 g1(EE/128, MT/128, 3);
    gemm_mma_kernel<<<g1, 256, DSMEM_G>>>(qb, kb, vb, nullptr, 0, 1);

    dim3 g2(SS/128, HH, BB);
    attn_mma_kernel<<<g2, 256, DSMEM_A>>>(pr, pc, rt);

    dim3 g3(EE/128, MT/128, 1);
    gemm_mma_kernel<<<g3, 256, DSMEM_G>>>(ob, ob, ob, out, 3, 0);
}